// round 14
// baseline (speedup 1.0000x reference)
#include <cuda_runtime.h>
#include <cuda_fp16.h>
#include <cstdint>

// Problem constants
#define BDIM   16
#define DDIM   256
#define TDIM   4096
#define NTOK   (BDIM * TDIM)   // 65536
#define NEMB   1024
#define NBOOKS 8

#define NEG_INF (-3.0e38f)
#define DELTA   6.0e-3f        // ~11 sigma of single-term fp16 score error

// Scratch
__device__ float g_resid[NTOK * DDIM];                  // 64 MB residual (N, D)
__device__ float g_cn[NBOOKS * NEMB];                   // 0.5*||e||^2
// fp16 codebooks, row-major [book][emb][k=256]
__device__ __half g_bh[NBOOKS * NEMB * DDIM];           // 4 MB

// ---------------------------------------------------------------------------
// helpers
// ---------------------------------------------------------------------------
__device__ __forceinline__ uint32_t smem_u32(const void* p) {
    uint32_t a;
    asm("{ .reg .u64 t; cvta.to.shared.u64 t, %1; cvt.u32.u64 %0, t; }" : "=r"(a) : "l"(p));
    return a;
}

#define LDSM4(r, addr)                                                         \
    asm volatile("ldmatrix.sync.aligned.m8n8.x4.shared.b16 {%0,%1,%2,%3}, [%4];" \
        : "=r"((r)[0]), "=r"((r)[1]), "=r"((r)[2]), "=r"((r)[3]) : "r"(addr))

#define MMA_F16(d, a, b0, b1)                                                  \
    asm volatile("mma.sync.aligned.m16n8k16.row.col.f32.f16.f16.f32 "          \
        "{%0,%1,%2,%3}, {%4,%5,%6,%7}, {%8,%9}, {%0,%1,%2,%3};"                \
        : "+f"((d)[0]), "+f"((d)[1]), "+f"((d)[2]), "+f"((d)[3])               \
        : "r"((a)[0]), "r"((a)[1]), "r"((a)[2]), "r"((a)[3]), "r"(b0), "r"(b1))

#define CP16(dst, src) asm volatile("cp.async.cg.shared.global [%0], [%1], 16;" :: "r"(dst), "l"(src))
#define CP_COMMIT()    asm volatile("cp.async.commit_group;" ::: "memory")
#define CP_WAIT0()     asm volatile("cp.async.wait_group 0;" ::: "memory")

// swizzle: 16B granule g (0..31) within a 512B row, row r
__device__ __forceinline__ int swzg(int g, int r) {
    return (((g & 24) | ((g & 7) ^ (r & 7)))) << 4;
}

__device__ __forceinline__ uint32_t pack_h2(float a, float b) {
    __half2 h2 = __halves2half2(__float2half_rn(a), __float2half_rn(b));
    return *reinterpret_cast<uint32_t*>(&h2);
}

// insert (s, i) into desc-sorted top-4 list; ties prefer lower index
__device__ __forceinline__ void ins4(float s, int i, float* v, int* ix) {
    bool g3 = (s > v[3]) || (s == v[3] && i < ix[3]);
    if (!g3) return;
    bool g1 = (s > v[1]) || (s == v[1] && i < ix[1]);
    if (g1) {
        bool g0 = (s > v[0]) || (s == v[0] && i < ix[0]);
        v[3] = v[2]; ix[3] = ix[2];
        v[2] = v[1]; ix[2] = ix[1];
        if (g0) { v[1] = v[0]; ix[1] = ix[0]; v[0] = s; ix[0] = i; }
        else    { v[1] = s; ix[1] = i; }
    } else {
        bool g2 = (s > v[2]) || (s == v[2] && i < ix[2]);
        if (g2) { v[3] = v[2]; ix[3] = ix[2]; v[2] = s; ix[2] = i; }
        else    { v[3] = s; ix[3] = i; }
    }
}

// ---------------------------------------------------------------------------
// transpose init / finish kernels (proven)
// ---------------------------------------------------------------------------
__global__ void init_resid(const float* __restrict__ z) {
    __shared__ float tile[32][33];
    const int b = blockIdx.z, d0 = blockIdx.y * 32, t0 = blockIdx.x * 32;
    const int tx = threadIdx.x, ty = threadIdx.y;
#pragma unroll
    for (int j = 0; j < 32; j += 8)
        tile[ty + j][tx] = z[(b * DDIM + d0 + ty + j) * TDIM + t0 + tx];
    __syncthreads();
#pragma unroll
    for (int j = 0; j < 32; j += 8)
        g_resid[(b * TDIM + t0 + ty + j) * DDIM + d0 + tx] = tile[tx][ty + j];
}

__global__ void write_out(const float* __restrict__ z, float* __restrict__ out) {
    __shared__ float tile[32][33];
    const int b = blockIdx.z, d0 = blockIdx.y * 32, t0 = blockIdx.x * 32;
    const int tx = threadIdx.x, ty = threadIdx.y;
#pragma unroll
    for (int j = 0; j < 32; j += 8)
        tile[ty + j][tx] = g_resid[(b * TDIM + t0 + ty + j) * DDIM + d0 + tx];
    __syncthreads();
#pragma unroll
    for (int j = 0; j < 32; j += 8) {
        int zi = (b * DDIM + d0 + ty + j) * TDIM + t0 + tx;
        out[zi] = z[zi] - tile[tx][ty + j];
    }
}

// per-embedding half squared norms + fp16 pack (1 warp = 1 embed row)
__global__ void prep_books(const float* __restrict__ books) {
    const int row  = blockIdx.x * 8 + (threadIdx.x >> 5);   // 0..8191
    const int lane = threadIdx.x & 31;
    const float4* er4 = (const float4*)(books + (size_t)row * DDIM);
    float4 v0 = er4[lane * 2];
    float4 v1 = er4[lane * 2 + 1];
    float s = v0.x*v0.x + v0.y*v0.y + v0.z*v0.z + v0.w*v0.w
            + v1.x*v1.x + v1.y*v1.y + v1.z*v1.z + v1.w*v1.w;
#pragma unroll
    for (int off = 16; off; off >>= 1) s += __shfl_xor_sync(0xffffffffu, s, off);
    if (lane == 0) g_cn[row] = 0.5f * s;

    uint4 H;
    H.x = pack_h2(v0.x, v0.y);
    H.y = pack_h2(v0.z, v0.w);
    H.z = pack_h2(v1.x, v1.y);
    H.w = pack_h2(v1.z, v1.w);
    *(uint4*)(g_bh + (size_t)row * DDIM + lane * 8) = H;
}

// ---------------------------------------------------------------------------
// Fused VQ step on mma.sync (fp16, single term) + top-4 candidate rescue
// 512 threads = 16 warps (4 token-rows x 4 embed-cols). CTA: 64 tok x 128 emb.
// Full-K B tiles: 8 stages/CTA. MMA floor halved vs 2-term split.
// ---------------------------------------------------------------------------
// smem byte layout.  rows are 512B (k-major, full K=256 fp16), swizzled
#define OFF_AH   0                 // 32 KB: 64 rows x 512B
#define OFF_B    32768             // 2 bufs x 64KB: 128 rows x 512B
#define OFF_CN   163840            // 2 x 128 f
#define OFF_TV   164864            // 64 tok x 64 entries f (16 KB)
#define OFF_TI   181248            // 64 tok x 64 entries i (16 KB)
#define OFF_BI   197632            // 64 i
#define SMEM_TC  197888

#define NTHREADS 512
#define TOK_CTA  64

__device__ __forceinline__ void copy_b_nt(uint32_t sbase, int book, int nt,
                                          int buf, int tid) {
    const __half* srcH = g_bh + (size_t)(book * NEMB + nt * 128) * DDIM;
#pragma unroll
    for (int u = 0; u < 8; u++) {
        int idx = tid + u * NTHREADS;     // 4096 granules: 128 rows x 32
        int r = idx >> 5, g = idx & 31;
        uint32_t dst = sbase + OFF_B + buf * 65536 + r * 512 + swzg(g, r);
        CP16(dst, srcH + (size_t)r * DDIM + g * 8);
    }
}

__global__ void __launch_bounds__(NTHREADS) vq_step_mma(const float* __restrict__ books,
                                                        const int* __restrict__ nbu,
                                                        int book) {
    if (book >= *nbu) return;
    extern __shared__ char smem[];
    const uint32_t sbase = smem_u32(smem);
    const int tid = threadIdx.x, lane = tid & 31, wid = tid >> 5;
    const int wr = wid & 3, wc = wid >> 2;           // 4 x 4 warp grid
    const int gid = lane >> 2, tg = lane & 3;
    const int tok0 = blockIdx.x * TOK_CTA;

    float* sCn = (float*)(smem + OFF_CN);
    float* sTV = (float*)(smem + OFF_TV);
    int*   sTI = (int*)(smem + OFF_TI);
    int*   sBI = (int*)(smem + OFF_BI);

    const float* cnb = g_cn + book * NEMB;

    // prologue: kick off B copy for stage 0, then stage A while it flies
    copy_b_nt(sbase, book, 0, 0, tid);
    CP_COMMIT();

    // ---- stage A: residual 64 tok x 256 k -> fp16, swizzled ----
#pragma unroll
    for (int u = 0; u < 4; u++) {
        int idx = tid + u * NTHREADS;     // 2048 16B-units: 64 rows x 32
        int t = idx >> 5, gg = idx & 31;
        const float4* rr = (const float4*)(g_resid + (size_t)(tok0 + t) * DDIM);
        float4 a = rr[gg * 2], b = rr[gg * 2 + 1];
        uint4 H;
        H.x = pack_h2(a.x, a.y);
        H.y = pack_h2(a.z, a.w);
        H.z = pack_h2(b.x, b.y);
        H.w = pack_h2(b.z, b.w);
        *(uint4*)(smem + OFF_AH + t * 512 + swzg(gg, t)) = H;
    }
    if (tid < 128) sCn[tid] = cnb[tid];   // norms for nt=0 (buffer 0)

    // ldmatrix per-lane address components
    const int xsw = lane & 7;
    const int kg  = lane >> 4;
    const uint32_t aBaseH = sbase + OFF_AH + (wr * 16 + (lane & 15)) * 512;
    const uint32_t bRow0  = (wc * 32 +      (lane & 15)) * 512;
    const uint32_t bRow1  = (wc * 32 + 16 + (lane & 15)) * 512;

    // per-thread top-4 for each of 2 token rows
    float tv[2][4];
    int   ti[2][4];
#pragma unroll
    for (int s = 0; s < 2; s++)
#pragma unroll
        for (int k = 0; k < 4; k++) { tv[s][k] = NEG_INF; ti[s][k] = 1 << 30; }

    // ---- 8-stage mainloop ----
    for (int nt = 0; nt < 8; nt++) {
        CP_WAIT0();          // B(nt) landed (only pending group)
        __syncthreads();     // B(nt), sCn(nt) visible; all done with stage nt-1

        if (nt + 1 < 8) {
            copy_b_nt(sbase, book, nt + 1, (nt + 1) & 1, tid);
            CP_COMMIT();
            if (tid < 128) sCn[((nt + 1) & 1) * 128 + tid] = cnb[(nt + 1) * 128 + tid];
        }

        float acc[4][4];
#pragma unroll
        for (int nbh = 0; nbh < 4; nbh++)
#pragma unroll
            for (int q = 0; q < 4; q++) acc[nbh][q] = 0.f;

        const uint32_t Bb = sbase + OFF_B + (nt & 1) * 65536;

#pragma unroll
        for (int ks = 0; ks < 16; ks++) {
            const int g = ks * 2 + kg;
            const int gsw = ((g & 24) | ((g & 7) ^ xsw)) << 4;
            uint32_t ah[4], bh0[4], bh1[4];
            LDSM4(ah,  aBaseH + gsw);
            LDSM4(bh0, Bb + bRow0 + gsw);
            LDSM4(bh1, Bb + bRow1 + gsw);

            MMA_F16(acc[0], ah, bh0[0], bh0[2]);
            MMA_F16(acc[1], ah, bh0[1], bh0[3]);
            MMA_F16(acc[2], ah, bh1[0], bh1[2]);
            MMA_F16(acc[3], ah, bh1[1], bh1[3]);
        }

        // fold this nt's 16 scores/thread into per-row top-4 (ascending index)
        const float* cn = sCn + (nt & 1) * 128 + wc * 32;
#pragma unroll
        for (int rh = 0; rh < 2; rh++)
#pragma unroll
            for (int nbh = 0; nbh < 4; nbh++)
#pragma unroll
                for (int c = 0; c < 2; c++) {
                    const int col = (nbh >> 1) * 16 + (nbh & 1) * 8 + tg * 2 + c;
                    float s = acc[nbh][rh * 2 + c] - cn[col];
                    int  ii = nt * 128 + wc * 32 + col;
                    ins4(s, ii, tv[rh], ti[rh]);
                }
    }

    // publish per-lane top-4 lists: token row -> 16 lists x 4 entries
#pragma unroll
    for (int s = 0; s < 2; s++) {
        int row  = wr * 16 + s * 8 + gid;
        int base = row * 64 + wc * 16 + tg * 4;
#pragma unroll
        for (int k = 0; k < 4; k++) {
            sTV[base + k] = tv[s][k];
            sTI[base + k] = ti[s][k];
        }
    }
    __syncthreads();

    // per-token final merge + (rare) exact top-4 rescore
    const float* ebk = books + (size_t)book * NEMB * DDIM;
    if (tid < TOK_CTA) {
        float v[4]; int ix[4];
#pragma unroll
        for (int k = 0; k < 4; k++) { v[k] = NEG_INF; ix[k] = 1 << 30; }
        const float* tvp = sTV + tid * 64;
        const int*   tip = sTI + tid * 64;
        for (int e = 0; e < 64; e++) ins4(tvp[e], tip[e], v, ix);

        int bi = ix[0];
        if (v[0] - v[1] <= DELTA) {
            // exact fp32 rescore of the 4 candidates
            const float4* rr = (const float4*)(g_resid + (size_t)(tok0 + tid) * DDIM);
            float best = NEG_INF; int bidx = 1 << 30;
#pragma unroll
            for (int c = 0; c < 4; c++) {
                const float4* er = (const float4*)(ebk + (size_t)ix[c] * DDIM);
                float a = 0.f;
#pragma unroll 8
                for (int k = 0; k < 64; k++) {
                    float4 x = rr[k], y = er[k];
                    a = fmaf(x.x, y.x, a); a = fmaf(x.y, y.y, a);
                    a = fmaf(x.z, y.z, a); a = fmaf(x.w, y.w, a);
                }
                float s = a - cnb[ix[c]];
                if (s > best || (s == best && ix[c] < bidx)) { best = s; bidx = ix[c]; }
            }
            bi = bidx;
        }
        sBI[tid] = bi;
    }
    __syncthreads();

    // residual update in place (exact fp32 codebook rows; L2-resident)
#pragma unroll
    for (int u = 0; u < 8; u++) {
        int i = tid + u * NTHREADS;       // 4096 = 64 tok x 64 float4
        int t = i >> 6, d4 = i & 63;
        int idx = sBI[t];
        float4 q = ((const float4*)(ebk + (size_t)idx * DDIM))[d4];
        float4* rp = ((float4*)(g_resid + (size_t)(tok0 + t) * DDIM)) + d4;
        float4 r = *rp;
        r.x -= q.x; r.y -= q.y; r.z -= q.z; r.w -= q.w;
        *rp = r;
    }
}

// ---------------------------------------------------------------------------
extern "C" void kernel_launch(void* const* d_in, const int* in_sizes, int n_in,
                              void* d_out, int out_size) {
    const float* z     = (const float*)d_in[0];
    const float* books = (const float*)d_in[1];
    const int*   nbu   = (const int*)d_in[2];
    float*       out   = (float*)d_out;

    cudaFuncSetAttribute(vq_step_mma, cudaFuncAttributeMaxDynamicSharedMemorySize, SMEM_TC);

    dim3 tgrid(TDIM / 32, DDIM / 32, BDIM);
    dim3 tblk(32, 8);

    init_resid<<<tgrid, tblk>>>(z);
    prep_books<<<(NBOOKS * NEMB) / 8, 256>>>(books);
    for (int k = 0; k < NBOOKS; k++)
        vq_step_mma<<<NTOK / TOK_CTA, NTHREADS, SMEM_TC>>>(books, nbu, k);
    write_out<<<tgrid, tblk>>>(z, out);
}

// round 15
// speedup vs baseline: 1.0018x; 1.0018x over previous
#include <cuda_runtime.h>
#include <cuda_fp16.h>
#include <cstdint>

// Problem constants
#define BDIM   16
#define DDIM   256
#define TDIM   4096
#define NTOK   (BDIM * TDIM)   // 65536
#define NEMB   1024
#define NBOOKS 8

#define NEG_INF (-3.0e38f)
#define DELTA   6.0e-3f        // ~11 sigma of single-term fp16 score error

// Padded fp16 codebook rows: 256 data + 8 pad halves = 264 (528B, 33 granules)
#define ROWH   264
#define ROWB   528
#define NTBYTES (128 * ROWB)   // 67584 bytes per (book, nt) chunk

// Scratch
__device__ float g_resid[NTOK * DDIM];                  // 64 MB residual (N, D)
__device__ float g_cn[NBOOKS * NEMB];                   // 0.5*||e||^2
__device__ __align__(16) __half g_bh[NBOOKS * NEMB * ROWH];   // padded fp16 books

// ---------------------------------------------------------------------------
// helpers
// ---------------------------------------------------------------------------
__device__ __forceinline__ uint32_t smem_u32(const void* p) {
    uint32_t a;
    asm("{ .reg .u64 t; cvta.to.shared.u64 t, %1; cvt.u32.u64 %0, t; }" : "=r"(a) : "l"(p));
    return a;
}

#define LDSM4(r, addr)                                                         \
    asm volatile("ldmatrix.sync.aligned.m8n8.x4.shared.b16 {%0,%1,%2,%3}, [%4];" \
        : "=r"((r)[0]), "=r"((r)[1]), "=r"((r)[2]), "=r"((r)[3]) : "r"(addr))

#define MMA_F16(d, a, b0, b1)                                                  \
    asm volatile("mma.sync.aligned.m16n8k16.row.col.f32.f16.f16.f32 "          \
        "{%0,%1,%2,%3}, {%4,%5,%6,%7}, {%8,%9}, {%0,%1,%2,%3};"                \
        : "+f"((d)[0]), "+f"((d)[1]), "+f"((d)[2]), "+f"((d)[3])               \
        : "r"((a)[0]), "r"((a)[1]), "r"((a)[2]), "r"((a)[3]), "r"(b0), "r"(b1))

// one-shot bulk copy gmem -> smem, completing on an mbarrier
#define BULK_G2S(dst, src, bytes, mbar)                                        \
    asm volatile("cp.async.bulk.shared::cluster.global.mbarrier::complete_tx::bytes " \
        "[%0], [%1], %2, [%3];"                                                \
        :: "r"(dst), "l"(src), "r"(bytes), "r"(mbar) : "memory")

#define MBAR_INIT(mb, c) asm volatile("mbarrier.init.shared.b64 [%0], %1;" :: "r"(mb), "r"(c) : "memory")
#define MBAR_EXPECT_TX(mb, tx) asm volatile("mbarrier.arrive.expect_tx.shared.b64 _, [%0], %1;" :: "r"(mb), "r"(tx) : "memory")

#define MBAR_WAIT(mb, par) do {                                                   \
    uint32_t _m = (mb), _p = (par), _d;                                           \
    asm volatile("{\n\t.reg .pred p;\n\t"                                         \
        "mbarrier.try_wait.parity.acquire.cta.shared::cta.b64 p, [%1], %2;\n\t"   \
        "selp.b32 %0, 1, 0, p;\n\t}" : "=r"(_d) : "r"(_m), "r"(_p) : "memory");   \
    if (!_d) {                                                                    \
        asm volatile("{\n\t.reg .pred P1;\n\tWL_%=:\n\t"                          \
            "mbarrier.try_wait.parity.acquire.cta.shared::cta.b64 P1, [%0], %1, 0x989680;\n\t" \
            "@P1 bra.uni WD_%=;\n\tbra.uni WL_%=;\n\tWD_%=:\n\t}"                 \
            :: "r"(_m), "r"(_p) : "memory");                                      \
    }                                                                             \
} while (0)

__device__ __forceinline__ uint32_t pack_h2(float a, float b) {
    __half2 h2 = __halves2half2(__float2half_rn(a), __float2half_rn(b));
    return *reinterpret_cast<uint32_t*>(&h2);
}

// insert (s, i) into desc-sorted top-4 list; ties prefer lower index
__device__ __forceinline__ void ins4(float s, int i, float* v, int* ix) {
    bool g3 = (s > v[3]) || (s == v[3] && i < ix[3]);
    if (!g3) return;
    bool g1 = (s > v[1]) || (s == v[1] && i < ix[1]);
    if (g1) {
        bool g0 = (s > v[0]) || (s == v[0] && i < ix[0]);
        v[3] = v[2]; ix[3] = ix[2];
        v[2] = v[1]; ix[2] = ix[1];
        if (g0) { v[1] = v[0]; ix[1] = ix[0]; v[0] = s; ix[0] = i; }
        else    { v[1] = s; ix[1] = i; }
    } else {
        bool g2 = (s > v[2]) || (s == v[2] && i < ix[2]);
        if (g2) { v[3] = v[2]; ix[3] = ix[2]; v[2] = s; ix[2] = i; }
        else    { v[3] = s; ix[3] = i; }
    }
}

// ---------------------------------------------------------------------------
// transpose init / finish kernels (proven)
// ---------------------------------------------------------------------------
__global__ void init_resid(const float* __restrict__ z) {
    __shared__ float tile[32][33];
    const int b = blockIdx.z, d0 = blockIdx.y * 32, t0 = blockIdx.x * 32;
    const int tx = threadIdx.x, ty = threadIdx.y;
#pragma unroll
    for (int j = 0; j < 32; j += 8)
        tile[ty + j][tx] = z[(b * DDIM + d0 + ty + j) * TDIM + t0 + tx];
    __syncthreads();
#pragma unroll
    for (int j = 0; j < 32; j += 8)
        g_resid[(b * TDIM + t0 + ty + j) * DDIM + d0 + tx] = tile[tx][ty + j];
}

__global__ void write_out(const float* __restrict__ z, float* __restrict__ out) {
    __shared__ float tile[32][33];
    const int b = blockIdx.z, d0 = blockIdx.y * 32, t0 = blockIdx.x * 32;
    const int tx = threadIdx.x, ty = threadIdx.y;
#pragma unroll
    for (int j = 0; j < 32; j += 8)
        tile[ty + j][tx] = g_resid[(b * TDIM + t0 + ty + j) * DDIM + d0 + tx];
    __syncthreads();
#pragma unroll
    for (int j = 0; j < 32; j += 8) {
        int zi = (b * DDIM + d0 + ty + j) * TDIM + t0 + tx;
        out[zi] = z[zi] - tile[tx][ty + j];
    }
}

// per-embedding half squared norms + padded fp16 pack (1 warp = 1 embed row)
__global__ void prep_books(const float* __restrict__ books) {
    const int row  = blockIdx.x * 8 + (threadIdx.x >> 5);   // 0..8191
    const int lane = threadIdx.x & 31;
    const float4* er4 = (const float4*)(books + (size_t)row * DDIM);
    float4 v0 = er4[lane * 2];
    float4 v1 = er4[lane * 2 + 1];
    float s = v0.x*v0.x + v0.y*v0.y + v0.z*v0.z + v0.w*v0.w
            + v1.x*v1.x + v1.y*v1.y + v1.z*v1.z + v1.w*v1.w;
#pragma unroll
    for (int off = 16; off; off >>= 1) s += __shfl_xor_sync(0xffffffffu, s, off);
    if (lane == 0) g_cn[row] = 0.5f * s;

    uint4 H;
    H.x = pack_h2(v0.x, v0.y);
    H.y = pack_h2(v0.z, v0.w);
    H.z = pack_h2(v1.x, v1.y);
    H.w = pack_h2(v1.z, v1.w);
    *(uint4*)(g_bh + (size_t)row * ROWH + lane * 8) = H;
    if (lane == 0)   // zero the 16B pad granule
        *(uint4*)(g_bh + (size_t)row * ROWH + 256) = make_uint4(0, 0, 0, 0);
}

// ---------------------------------------------------------------------------
// Fused VQ step: single-term fp16 mma.sync + top-4 candidate rescue.
// B streamed via cp.async.bulk (1 instr / 67.5KB stage) into 528B-padded rows
// (33 granules, co-prime with 32 banks -> conflict-free LDSM, no swizzle).
// 512 threads = 16 warps (4 token-rows x 4 embed-cols). CTA: 64 tok x 128 emb.
// ---------------------------------------------------------------------------
#define OFF_A    0                 // 64 rows x 528B = 33792
#define OFF_B    33792             // 2 bufs x 67584 = 135168
#define OFF_MB   168960            // 2 x u64 mbarriers (+pad)
#define OFF_CN   168992            // 2 x 128 f
#define OFF_TV   170016            // 64 tok x 64 entries f (16 KB)
#define OFF_TI   186400            // 64 tok x 64 entries i (16 KB)
#define OFF_BI   202784            // 64 i
#define SMEM_TC  203072

#define NTHREADS 512
#define TOK_CTA  64

__global__ void __launch_bounds__(NTHREADS) vq_step_mma(const float* __restrict__ books,
                                                        const int* __restrict__ nbu,
                                                        int book) {
    if (book >= *nbu) return;
    extern __shared__ char smem[];
    const uint32_t sbase = smem_u32(smem);
    const int tid = threadIdx.x, lane = tid & 31, wid = tid >> 5;
    const int wr = wid & 3, wc = wid >> 2;           // 4 x 4 warp grid
    const int gid = lane >> 2, tg = lane & 3;
    const int tok0 = blockIdx.x * TOK_CTA;

    float* sCn = (float*)(smem + OFF_CN);
    float* sTV = (float*)(smem + OFF_TV);
    int*   sTI = (int*)(smem + OFF_TI);
    int*   sBI = (int*)(smem + OFF_BI);

    const float* cnb = g_cn + book * NEMB;
    const __half* bkB = g_bh + (size_t)book * NEMB * ROWH;

    // mbarriers (one per B buffer)
    if (tid == 0) {
        MBAR_INIT(sbase + OFF_MB, 1);
        MBAR_INIT(sbase + OFF_MB + 8, 1);
    }
    __syncthreads();

    // prologue: issue B copy for nt=0
    if (tid == 0) {
        MBAR_EXPECT_TX(sbase + OFF_MB, (uint32_t)NTBYTES);
        BULK_G2S(sbase + OFF_B, (const void*)bkB, (uint32_t)NTBYTES, sbase + OFF_MB);
    }

    // ---- stage A: residual 64 tok x 256 k -> fp16, padded rows ----
#pragma unroll
    for (int u = 0; u < 4; u++) {
        int idx = tid + u * NTHREADS;     // 2048 16B-units: 64 rows x 32
        int t = idx >> 5, gg = idx & 31;
        const float4* rr = (const float4*)(g_resid + (size_t)(tok0 + t) * DDIM);
        float4 a = rr[gg * 2], b = rr[gg * 2 + 1];
        uint4 H;
        H.x = pack_h2(a.x, a.y);
        H.y = pack_h2(a.z, a.w);
        H.z = pack_h2(b.x, b.y);
        H.w = pack_h2(b.z, b.w);
        *(uint4*)(smem + OFF_A + t * ROWB + gg * 16) = H;
    }
    if (tid < 128) sCn[tid] = cnb[tid];   // norms for nt=0 (buffer 0)

    // ldmatrix per-lane address components (no swizzle: 33-granule rows)
    const int kg = lane >> 4;
    const uint32_t aBase = sbase + OFF_A + (wr * 16 + (lane & 15)) * ROWB;
    const uint32_t bRow0 = (wc * 32 +      (lane & 15)) * ROWB;
    const uint32_t bRow1 = (wc * 32 + 16 + (lane & 15)) * ROWB;

    // per-thread top-4 for each of 2 token rows
    float tv[2][4];
    int   ti[2][4];
#pragma unroll
    for (int s = 0; s < 2; s++)
#pragma unroll
        for (int k = 0; k < 4; k++) { tv[s][k] = NEG_INF; ti[s][k] = 1 << 30; }

    // ---- 8-stage mainloop ----
    for (int nt = 0; nt < 8; nt++) {
        const int buf = nt & 1;
        __syncthreads();     // all done reading buf^1 (stage nt-1); A staged (nt=0)

        if (tid == 0 && nt + 1 < 8) {
            const uint32_t mb1 = sbase + OFF_MB + (buf ^ 1) * 8;
            MBAR_EXPECT_TX(mb1, (uint32_t)NTBYTES);
            BULK_G2S(sbase + OFF_B + (buf ^ 1) * NTBYTES,
                     (const void*)(bkB + (size_t)(nt + 1) * 128 * ROWH),
                     (uint32_t)NTBYTES, mb1);
        }
        if (nt + 1 < 8 && tid < 128)
            sCn[((nt + 1) & 1) * 128 + tid] = cnb[(nt + 1) * 128 + tid];

        MBAR_WAIT(sbase + OFF_MB + buf * 8, (nt >> 1) & 1);   // B(nt) landed

        float acc[4][4];
#pragma unroll
        for (int nbh = 0; nbh < 4; nbh++)
#pragma unroll
            for (int q = 0; q < 4; q++) acc[nbh][q] = 0.f;

        const uint32_t Bb = sbase + OFF_B + buf * NTBYTES;

#pragma unroll
        for (int ks = 0; ks < 16; ks++) {
            const int goff = (ks * 2 + kg) * 16;
            uint32_t ah[4], bh0[4], bh1[4];
            LDSM4(ah,  aBase + goff);
            LDSM4(bh0, Bb + bRow0 + goff);
            LDSM4(bh1, Bb + bRow1 + goff);

            MMA_F16(acc[0], ah, bh0[0], bh0[2]);
            MMA_F16(acc[1], ah, bh0[1], bh0[3]);
            MMA_F16(acc[2], ah, bh1[0], bh1[2]);
            MMA_F16(acc[3], ah, bh1[1], bh1[3]);
        }

        // fold this nt's 16 scores/thread into per-row top-4
        const float* cn = sCn + buf * 128 + wc * 32;
#pragma unroll
        for (int rh = 0; rh < 2; rh++)
#pragma unroll
            for (int nbh = 0; nbh < 4; nbh++)
#pragma unroll
                for (int c = 0; c < 2; c++) {
                    const int col = (nbh >> 1) * 16 + (nbh & 1) * 8 + tg * 2 + c;
                    float s = acc[nbh][rh * 2 + c] - cn[col];
                    int  ii = nt * 128 + wc * 32 + col;
                    ins4(s, ii, tv[rh], ti[rh]);
                }
    }

    // publish per-lane top-4 lists: token row -> 16 lists x 4 entries
#pragma unroll
    for (int s = 0; s < 2; s++) {
        int row  = wr * 16 + s * 8 + gid;
        int base = row * 64 + wc * 16 + tg * 4;
#pragma unroll
        for (int k = 0; k < 4; k++) {
            sTV[base + k] = tv[s][k];
            sTI[base + k] = ti[s][k];
        }
    }
    __syncthreads();

    // per-token final merge + (rare) exact top-4 rescore
    const float* ebk = books + (size_t)book * NEMB * DDIM;
    if (tid < TOK_CTA) {
        float v[4]; int ix[4];
#pragma unroll
        for (int k = 0; k < 4; k++) { v[k] = NEG_INF; ix[k] = 1 << 30; }
        const float* tvp = sTV + tid * 64;
        const int*   tip = sTI + tid * 64;
        for (int e = 0; e < 64; e++) ins4(tvp[e], tip[e], v, ix);

        int bi = ix[0];
        if (v[0] - v[1] <= DELTA) {
            // exact fp32 rescore of the 4 candidates
            const float4* rr = (const float4*)(g_resid + (size_t)(tok0 + tid) * DDIM);
            float best = NEG_INF; int bidx = 1 << 30;
#pragma unroll
            for (int c = 0; c < 4; c++) {
                const float4* er = (const float4*)(ebk + (size_t)ix[c] * DDIM);
                float a = 0.f;
#pragma unroll 8
                for (int k = 0; k < 64; k++) {
                    float4 x = rr[k], y = er[k];
                    a = fmaf(x.x, y.x, a); a = fmaf(x.y, y.y, a);
                    a = fmaf(x.z, y.z, a); a = fmaf(x.w, y.w, a);
                }
                float s = a - cnb[ix[c]];
                if (s > best || (s == best && ix[c] < bidx)) { best = s; bidx = ix[c]; }
            }
            bi = bidx;
        }
        sBI[tid] = bi;
    }
    __syncthreads();

    // residual update in place (exact fp32 codebook rows; L2-resident)
#pragma unroll
    for (int u = 0; u < 8; u++) {
        int i = tid + u * NTHREADS;       // 4096 = 64 tok x 64 float4
        int t = i >> 6, d4 = i & 63;
        int idx = sBI[t];
        float4 q = ((const float4*)(ebk + (size_t)idx * DDIM))[d4];
        float4* rp = ((float4*)(g_resid + (size_t)(tok0 + t) * DDIM)) + d4;
        float4 r = *rp;
        r.x -= q.x; r.y -= q.y; r.z -= q.z; r.w -= q.w;
        *rp = r;
    }
}

// ---------------------------------------------------------------------------
extern "C" void kernel_launch(void* const* d_in, const int* in_sizes, int n_in,
                              void* d_out, int out_size) {
    const float* z     = (const float*)d_in[0];
    const float* books = (const float*)d_in[1];
    const int*   nbu   = (const int*)d_in[2];
    float*       out   = (float*)d_out;

    cudaFuncSetAttribute(vq_step_mma, cudaFuncAttributeMaxDynamicSharedMemorySize, SMEM_TC);

    dim3 tgrid(TDIM / 32, DDIM / 32, BDIM);
    dim3 tblk(32, 8);

    init_resid<<<tgrid, tblk>>>(z);
    prep_books<<<(NBOOKS * NEMB) / 8, 256>>>(books);
    for (int k = 0; k < NBOOKS; k++)
        vq_step_mma<<<NTOK / TOK_CTA, NTHREADS, SMEM_TC>>>(books, nbu, k);
    write_out<<<tgrid, tblk>>>(z, out);
}

// round 16
// speedup vs baseline: 1.8309x; 1.8275x over previous
#include <cuda_runtime.h>
#include <cuda_fp16.h>
#include <cstdint>

// Problem constants
#define BDIM   16
#define DDIM   256
#define TDIM   4096
#define NTOK   (BDIM * TDIM)   // 65536
#define NEMB   1024
#define NBOOKS 8

#define NEG_INF (-3.0e38f)
#define DELTA   6.0e-3f        // ~11 sigma of single-term fp16 score error

// Padded fp16 codebook rows: 256 data + 8 pad halves = 264 (528B, 33 granules)
#define ROWH   264
#define ROWB   528
#define NTBYTES (64 * ROWB)    // 33792 bytes per (book, 64-emb stage) chunk

// Scratch
__device__ float g_resid[NTOK * DDIM];                  // 64 MB residual (N, D)
__device__ float g_cn[NBOOKS * NEMB];                   // 0.5*||e||^2
__device__ __align__(16) __half g_bh[NBOOKS * NEMB * ROWH];   // padded fp16 books

// ---------------------------------------------------------------------------
// helpers
// ---------------------------------------------------------------------------
__device__ __forceinline__ uint32_t smem_u32(const void* p) {
    uint32_t a;
    asm("{ .reg .u64 t; cvta.to.shared.u64 t, %1; cvt.u32.u64 %0, t; }" : "=r"(a) : "l"(p));
    return a;
}

#define LDSM4(r, addr)                                                         \
    asm volatile("ldmatrix.sync.aligned.m8n8.x4.shared.b16 {%0,%1,%2,%3}, [%4];" \
        : "=r"((r)[0]), "=r"((r)[1]), "=r"((r)[2]), "=r"((r)[3]) : "r"(addr))

#define MMA_F16(d, a, b0, b1)                                                  \
    asm volatile("mma.sync.aligned.m16n8k16.row.col.f32.f16.f16.f32 "          \
        "{%0,%1,%2,%3}, {%4,%5,%6,%7}, {%8,%9}, {%0,%1,%2,%3};"                \
        : "+f"((d)[0]), "+f"((d)[1]), "+f"((d)[2]), "+f"((d)[3])               \
        : "r"((a)[0]), "r"((a)[1]), "r"((a)[2]), "r"((a)[3]), "r"(b0), "r"(b1))

// one-shot bulk copy gmem -> smem, completing on an mbarrier
#define BULK_G2S(dst, src, bytes, mbar)                                        \
    asm volatile("cp.async.bulk.shared::cluster.global.mbarrier::complete_tx::bytes " \
        "[%0], [%1], %2, [%3];"                                                \
        :: "r"(dst), "l"(src), "r"(bytes), "r"(mbar) : "memory")

#define MBAR_INIT(mb, c) asm volatile("mbarrier.init.shared.b64 [%0], %1;" :: "r"(mb), "r"(c) : "memory")
#define MBAR_EXPECT_TX(mb, tx) asm volatile("mbarrier.arrive.expect_tx.shared.b64 _, [%0], %1;" :: "r"(mb), "r"(tx) : "memory")

#define MBAR_WAIT(mb, par) do {                                                   \
    uint32_t _m = (mb), _p = (par), _d;                                           \
    asm volatile("{\n\t.reg .pred p;\n\t"                                         \
        "mbarrier.try_wait.parity.acquire.cta.shared::cta.b64 p, [%1], %2;\n\t"   \
        "selp.b32 %0, 1, 0, p;\n\t}" : "=r"(_d) : "r"(_m), "r"(_p) : "memory");   \
    if (!_d) {                                                                    \
        asm volatile("{\n\t.reg .pred P1;\n\tWL_%=:\n\t"                          \
            "mbarrier.try_wait.parity.acquire.cta.shared::cta.b64 P1, [%0], %1, 0x989680;\n\t" \
            "@P1 bra.uni WD_%=;\n\tbra.uni WL_%=;\n\tWD_%=:\n\t}"                 \
            :: "r"(_m), "r"(_p) : "memory");                                      \
    }                                                                             \
} while (0)

__device__ __forceinline__ uint32_t pack_h2(float a, float b) {
    __half2 h2 = __halves2half2(__float2half_rn(a), __float2half_rn(b));
    return *reinterpret_cast<uint32_t*>(&h2);
}

// merge another (v1,i1,v2,i2) top-2 tuple into ours (values only need be >=)
__device__ __forceinline__ void top2_merge4(float& v1, int& i1, float& v2, int& i2,
                                            float ov1, int oi1, float ov2, int oi2) {
    if (ov1 > v1) {
        if (v1 > ov2) { v2 = v1; i2 = i1; }
        else          { v2 = ov2; i2 = oi2; }
        v1 = ov1; i1 = oi1;
    } else if (ov1 > v2) {
        v2 = ov1; i2 = oi1;
    }
}

// ---------------------------------------------------------------------------
// transpose init / finish kernels (proven)
// ---------------------------------------------------------------------------
__global__ void init_resid(const float* __restrict__ z) {
    __shared__ float tile[32][33];
    const int b = blockIdx.z, d0 = blockIdx.y * 32, t0 = blockIdx.x * 32;
    const int tx = threadIdx.x, ty = threadIdx.y;
#pragma unroll
    for (int j = 0; j < 32; j += 8)
        tile[ty + j][tx] = z[(b * DDIM + d0 + ty + j) * TDIM + t0 + tx];
    __syncthreads();
#pragma unroll
    for (int j = 0; j < 32; j += 8)
        g_resid[(b * TDIM + t0 + ty + j) * DDIM + d0 + tx] = tile[tx][ty + j];
}

__global__ void write_out(const float* __restrict__ z, float* __restrict__ out) {
    __shared__ float tile[32][33];
    const int b = blockIdx.z, d0 = blockIdx.y * 32, t0 = blockIdx.x * 32;
    const int tx = threadIdx.x, ty = threadIdx.y;
#pragma unroll
    for (int j = 0; j < 32; j += 8)
        tile[ty + j][tx] = g_resid[(b * TDIM + t0 + ty + j) * DDIM + d0 + tx];
    __syncthreads();
#pragma unroll
    for (int j = 0; j < 32; j += 8) {
        int zi = (b * DDIM + d0 + ty + j) * TDIM + t0 + tx;
        out[zi] = z[zi] - tile[tx][ty + j];
    }
}

// per-embedding half squared norms + padded fp16 pack (1 warp = 1 embed row)
__global__ void prep_books(const float* __restrict__ books) {
    const int row  = blockIdx.x * 8 + (threadIdx.x >> 5);   // 0..8191
    const int lane = threadIdx.x & 31;
    const float4* er4 = (const float4*)(books + (size_t)row * DDIM);
    float4 v0 = er4[lane * 2];
    float4 v1 = er4[lane * 2 + 1];
    float s = v0.x*v0.x + v0.y*v0.y + v0.z*v0.z + v0.w*v0.w
            + v1.x*v1.x + v1.y*v1.y + v1.z*v1.z + v1.w*v1.w;
#pragma unroll
    for (int off = 16; off; off >>= 1) s += __shfl_xor_sync(0xffffffffu, s, off);
    if (lane == 0) g_cn[row] = 0.5f * s;

    uint4 H;
    H.x = pack_h2(v0.x, v0.y);
    H.y = pack_h2(v0.z, v0.w);
    H.z = pack_h2(v1.x, v1.y);
    H.w = pack_h2(v1.z, v1.w);
    *(uint4*)(g_bh + (size_t)row * ROWH + lane * 8) = H;
    if (lane == 0)   // zero the 16B pad granule
        *(uint4*)(g_bh + (size_t)row * ROWH + 256) = make_uint4(0, 0, 0, 0);
}

// ---------------------------------------------------------------------------
// Fused VQ step: single-term fp16 mma.sync + top-2/candidate rescue.
// 2 CTAs/SM (104KB smem each): independent barrier domains hide latency.
// 512 threads = 16 warps (4 token-rows x 4 embed-cols). CTA: 64 tok.
// 16 stages x 64 embeds; B via cp.async.bulk into 528B-padded rows.
// ---------------------------------------------------------------------------
#define OFF_A    0                 // 64 rows x 528B = 33792
#define OFF_B    33792             // 2 bufs x 33792 = 67584 -> end 101376
#define OFF_MB   101376            // 2 x u64 mbarriers (+pad to 32)
#define OFF_CN   101408            // 2 x 64 f = 512
#define OFF_V    101920            // 64 tok x 4 wc x (v1,i1,v2,i2) = 4096
#define OFF_BI   106016            // 64 i
#define SMEM_TC  106272

#define NTHREADS 512
#define TOK_CTA  64

__global__ void __launch_bounds__(NTHREADS, 2) vq_step_mma(const float* __restrict__ books,
                                                           const int* __restrict__ nbu,
                                                           int book) {
    if (book >= *nbu) return;
    extern __shared__ char smem[];
    const uint32_t sbase = smem_u32(smem);
    const int tid = threadIdx.x, lane = tid & 31, wid = tid >> 5;
    const int wr = wid & 3, wc = wid >> 2;           // 4 x 4 warp grid
    const int gid = lane >> 2, tg = lane & 3;
    const int tok0 = blockIdx.x * TOK_CTA;

    float* sCn = (float*)(smem + OFF_CN);
    float4* sV = (float4*)(smem + OFF_V);            // (v1, i1(asint), v2, i2)
    int*   sBI = (int*)(smem + OFF_BI);

    const float* cnb = g_cn + book * NEMB;
    const __half* bkB = g_bh + (size_t)book * NEMB * ROWH;

    if (tid == 0) {
        MBAR_INIT(sbase + OFF_MB, 1);
        MBAR_INIT(sbase + OFF_MB + 8, 1);
    }
    __syncthreads();

    // prologue: issue B copy for stage 0
    if (tid == 0) {
        MBAR_EXPECT_TX(sbase + OFF_MB, (uint32_t)NTBYTES);
        BULK_G2S(sbase + OFF_B, (const void*)bkB, (uint32_t)NTBYTES, sbase + OFF_MB);
    }

    // ---- stage A: residual 64 tok x 256 k -> fp16, padded rows ----
#pragma unroll
    for (int u = 0; u < 4; u++) {
        int idx = tid + u * NTHREADS;     // 2048 16B-units: 64 rows x 32
        int t = idx >> 5, gg = idx & 31;
        const float4* rr = (const float4*)(g_resid + (size_t)(tok0 + t) * DDIM);
        float4 a = rr[gg * 2], b = rr[gg * 2 + 1];
        uint4 H;
        H.x = pack_h2(a.x, a.y);
        H.y = pack_h2(a.z, a.w);
        H.z = pack_h2(b.x, b.y);
        H.w = pack_h2(b.z, b.w);
        *(uint4*)(smem + OFF_A + t * ROWB + gg * 16) = H;
    }
    if (tid < 64) sCn[tid] = cnb[tid];    // norms for stage 0 (buffer 0)

    // ldmatrix per-lane address components (no swizzle: 33-granule rows)
    const int kg = lane >> 4;
    const uint32_t aBase = sbase + OFF_A + (wr * 16 + (lane & 15)) * ROWB;
    const uint32_t bRow  = (wc * 16 + (lane & 15)) * ROWB;

    // per-thread running top-2 (with indices) for each of 2 token rows
    float tv1[2], tv2[2];
    int   ti1[2], ti2[2];
#pragma unroll
    for (int s = 0; s < 2; s++) {
        tv1[s] = NEG_INF; tv2[s] = NEG_INF;
        ti1[s] = 1 << 30; ti2[s] = 1 << 30;
    }

    // ---- 16-stage mainloop (64 embeds per stage) ----
    for (int nt = 0; nt < 16; nt++) {
        const int buf = nt & 1;
        __syncthreads();     // all done reading buf^1 (stage nt-1); A staged (nt=0)

        if (tid == 0 && nt + 1 < 16) {
            const uint32_t mb1 = sbase + OFF_MB + (buf ^ 1) * 8;
            MBAR_EXPECT_TX(mb1, (uint32_t)NTBYTES);
            BULK_G2S(sbase + OFF_B + (buf ^ 1) * NTBYTES,
                     (const void*)(bkB + (size_t)(nt + 1) * 64 * ROWH),
                     (uint32_t)NTBYTES, mb1);
        }
        if (nt + 1 < 16 && tid < 64)
            sCn[((nt + 1) & 1) * 64 + tid] = cnb[(nt + 1) * 64 + tid];

        MBAR_WAIT(sbase + OFF_MB + buf * 8, (nt >> 1) & 1);   // B(nt) landed

        float acc[2][4];
#pragma unroll
        for (int h = 0; h < 2; h++)
#pragma unroll
            for (int q = 0; q < 4; q++) acc[h][q] = 0.f;

        const uint32_t Bb = sbase + OFF_B + buf * NTBYTES;

#pragma unroll
        for (int ks = 0; ks < 16; ks++) {
            const int goff = (ks * 2 + kg) * 16;
            uint32_t ah[4], bh[4];
            LDSM4(ah, aBase + goff);
            LDSM4(bh, Bb + bRow + goff);

            MMA_F16(acc[0], ah, bh[0], bh[2]);
            MMA_F16(acc[1], ah, bh[1], bh[3]);
        }

        // fold this stage's 8 scores/thread into running top-2 (select-based)
        const float* cn = sCn + buf * 64 + wc * 16;
#pragma unroll
        for (int rh = 0; rh < 2; rh++)
#pragma unroll
            for (int h = 0; h < 2; h++)
#pragma unroll
                for (int c = 0; c < 2; c++) {
                    const int col = h * 8 + tg * 2 + c;
                    float s = acc[h][rh * 2 + c] - cn[col];
                    int  ii = nt * 64 + wc * 16 + col;
                    if (s > tv1[rh]) {
                        tv2[rh] = tv1[rh]; ti2[rh] = ti1[rh];
                        tv1[rh] = s;       ti1[rh] = ii;
                    } else if (s > tv2[rh]) {
                        tv2[rh] = s; ti2[rh] = ii;
                    }
                }
    }

    // merge top-2 across the 4 quad lanes (same token rows, different cols)
#pragma unroll
    for (int off = 1; off <= 2; off <<= 1)
#pragma unroll
        for (int s = 0; s < 2; s++) {
            float ov1 = __shfl_xor_sync(0xffffffffu, tv1[s], off);
            int   oi1 = __shfl_xor_sync(0xffffffffu, ti1[s], off);
            float ov2 = __shfl_xor_sync(0xffffffffu, tv2[s], off);
            int   oi2 = __shfl_xor_sync(0xffffffffu, ti2[s], off);
            top2_merge4(tv1[s], ti1[s], tv2[s], ti2[s], ov1, oi1, ov2, oi2);
        }
    __syncthreads();   // mainloop fully drained before sV reuse of timeline
    if (tg == 0) {
#pragma unroll
        for (int s = 0; s < 2; s++) {
            int row = wr * 16 + s * 8 + gid;
            sV[row * 4 + wc] = make_float4(tv1[s], __int_as_float(ti1[s]),
                                           tv2[s], __int_as_float(ti2[s]));
        }
    }
    __syncthreads();

    // per-token final merge + (rare) exact candidate rescore
    const float* ebk = books + (size_t)book * NEMB * DDIM;
    if (tid < TOK_CTA) {
        float4 e0 = sV[tid * 4];
        float V1 = e0.x; int I1 = __float_as_int(e0.y);
        float V2 = e0.z; int I2 = __float_as_int(e0.w);
        int cand[8];
        cand[0] = I1; cand[4] = I2;
#pragma unroll
        for (int w = 1; w < 4; w++) {
            float4 e = sV[tid * 4 + w];
            cand[w] = __float_as_int(e.y);
            cand[4 + w] = __float_as_int(e.w);
            top2_merge4(V1, I1, V2, I2,
                        e.x, __float_as_int(e.y), e.z, __float_as_int(e.w));
        }

        int bi = I1;
        if (V1 - V2 <= DELTA) {
            // exact fp32 rescore of the 8 candidate rows
            const float4* rr = (const float4*)(g_resid + (size_t)(tok0 + tid) * DDIM);
            float best = NEG_INF; int bidx = 1 << 30;
#pragma unroll
            for (int c = 0; c < 8; c++) {
                const float4* er = (const float4*)(ebk + (size_t)cand[c] * DDIM);
                float a = 0.f;
#pragma unroll 8
                for (int k = 0; k < 64; k++) {
                    float4 x = rr[k], y = er[k];
                    a = fmaf(x.x, y.x, a); a = fmaf(x.y, y.y, a);
                    a = fmaf(x.z, y.z, a); a = fmaf(x.w, y.w, a);
                }
                float s = a - cnb[cand[c]];
                if (s > best || (s == best && cand[c] < bidx)) { best = s; bidx = cand[c]; }
            }
            bi = bidx;
        }
        sBI[tid] = bi;
    }
    __syncthreads();

    // residual update in place (exact fp32 codebook rows; L2-resident)
#pragma unroll
    for (int u = 0; u < 8; u++) {
        int i = tid + u * NTHREADS;       // 4096 = 64 tok x 64 float4
        int t = i >> 6, d4 = i & 63;
        int idx = sBI[t];
        float4 q = ((const float4*)(ebk + (size_t)idx * DDIM))[d4];
        float4* rp = ((float4*)(g_resid + (size_t)(tok0 + t) * DDIM)) + d4;
        float4 r = *rp;
        r.x -= q.x; r.y -= q.y; r.z -= q.z; r.w -= q.w;
        *rp = r;
    }
}

// ---------------------------------------------------------------------------
extern "C" void kernel_launch(void* const* d_in, const int* in_sizes, int n_in,
                              void* d_out, int out_size) {
    const float* z     = (const float*)d_in[0];
    const float* books = (const float*)d_in[1];
    const int*   nbu   = (const int*)d_in[2];
    float*       out   = (float*)d_out;

    cudaFuncSetAttribute(vq_step_mma, cudaFuncAttributeMaxDynamicSharedMemorySize, SMEM_TC);

    dim3 tgrid(TDIM / 32, DDIM / 32, BDIM);
    dim3 tblk(32, 8);

    init_resid<<<tgrid, tblk>>>(z);
    prep_books<<<(NBOOKS * NEMB) / 8, 256>>>(books);
    for (int k = 0; k < NBOOKS; k++)
        vq_step_mma<<<NTOK / TOK_CTA, NTHREADS, SMEM_TC>>>(books, nbu, k);
    write_out<<<tgrid, tblk>>>(z, out);
}